// round 9
// baseline (speedup 1.0000x reference)
#include <cuda_runtime.h>

#define N_ITEMS  200000
#define EMB      100
#define BATCH    100
#define HIST_MAX 50
#define NNZ_A    6400000
#define NNZ_H    25000
#define NCHUNKS  ((N_ITEMS + 1023) / 1024)

// ---------------- device scratch (no allocations allowed) ----------------
__device__ int   g_cnt[N_ITEMS];
__device__ int   g_rowstart[N_ITEMS + 1];
__device__ int   g_cursor[N_ITEMS];
__device__ int   g_chunksums[NCHUNKS];
__device__ int2  g_edges[NNZ_A];                    // (col, val-as-int) sorted by row
__device__ float g_buf0[(size_t)N_ITEMS * EMB];
__device__ float g_buf1[(size_t)N_ITEMS * EMB];
__device__ float g_hist[BATCH * HIST_MAX * EMB];

// ---------------- CSR build: histogram + scan + scatter ----------------
__global__ void k_zero_cnt() {
    int i = blockIdx.x * blockDim.x + threadIdx.x;
    if (i < N_ITEMS) g_cnt[i] = 0;
}

__global__ void k_count(const int* __restrict__ rows) {
    int i = blockIdx.x * blockDim.x + threadIdx.x;
    if (i < NNZ_A) atomicAdd(&g_cnt[rows[i]], 1);
}

// per-chunk (1024) sums
__global__ void k_scan1() {
    __shared__ int wsum[32];
    int tid = threadIdx.x, lane = tid & 31, w = tid >> 5;
    int i = blockIdx.x * 1024 + tid;
    int v = (i < N_ITEMS) ? g_cnt[i] : 0;
    for (int o = 16; o; o >>= 1) v += __shfl_down_sync(0xFFFFFFFFu, v, o);
    if (lane == 0) wsum[w] = v;
    __syncthreads();
    if (w == 0) {
        int s = wsum[lane];
        for (int o = 16; o; o >>= 1) s += __shfl_down_sync(0xFFFFFFFFu, s, o);
        if (lane == 0) g_chunksums[blockIdx.x] = s;
    }
}

// serial exclusive scan of 196 chunk sums (tiny)
__global__ void k_scan2() {
    if (threadIdx.x == 0) {
        int run = 0;
        for (int i = 0; i < NCHUNKS; i++) {
            int v = g_chunksums[i];
            g_chunksums[i] = run;
            run += v;
        }
        g_rowstart[N_ITEMS] = run;
    }
}

// per-chunk exclusive scan + chunk offset -> row_start / cursor
__global__ void k_scan3() {
    __shared__ int wsum[32];
    int tid = threadIdx.x, lane = tid & 31, w = tid >> 5;
    int i = blockIdx.x * 1024 + tid;
    int v = (i < N_ITEMS) ? g_cnt[i] : 0;
    int x = v;
    for (int o = 1; o < 32; o <<= 1) {
        int y = __shfl_up_sync(0xFFFFFFFFu, x, o);
        if (lane >= o) x += y;
    }
    if (lane == 31) wsum[w] = x;
    __syncthreads();
    if (w == 0) {
        int s = wsum[lane];
        for (int o = 1; o < 32; o <<= 1) {
            int y = __shfl_up_sync(0xFFFFFFFFu, s, o);
            if (lane >= o) s += y;
        }
        wsum[lane] = s;   // inclusive warp sums
    }
    __syncthreads();
    int woff = (w == 0) ? 0 : wsum[w - 1];
    int excl = x - v + woff + g_chunksums[blockIdx.x];
    if (i < N_ITEMS) {
        g_rowstart[i] = excl;
        g_cursor[i]   = excl;
    }
}

__global__ void k_scatter(const int* __restrict__ rows,
                          const int* __restrict__ cols,
                          const float* __restrict__ vals) {
    int i = blockIdx.x * blockDim.x + threadIdx.x;
    if (i >= NNZ_A) return;
    int r = rows[i];
    int p = atomicAdd(&g_cursor[r], 1);
    g_edges[p] = make_int2(cols[i], __float_as_int(vals[i]));
}

// ---------------- acc init: out = embedding * gamma[0] ----------------
__global__ void k_init_acc(const float4* __restrict__ emb4,
                           const float* __restrict__ gamma,
                           float4* __restrict__ out4) {
    size_t i = (size_t)blockIdx.x * blockDim.x + threadIdx.x;
    const size_t n4 = (size_t)N_ITEMS * EMB / 4;   // 5,000,000
    float g = gamma[0];
    if (i < n4) {
        float4 e = emb4[i];
        out4[i] = make_float4(e.x * g, e.y * g, e.z * g, e.w * g);
    }
}

// ---------------- CSR SpMM: warp per row, fused gamma + acc ----------------
__global__ void k_spmm(const float* __restrict__ x,
                       float* __restrict__ y,            // may be null (last layer)
                       float* __restrict__ acc,
                       const float* __restrict__ gammap) {
    int row  = blockIdx.x * (blockDim.x >> 5) + (threadIdx.x >> 5);
    int lane = threadIdx.x & 31;
    if (row >= N_ITEMS) return;
    float g = *gammap;
    int s = g_rowstart[row], e = g_rowstart[row + 1];

    float a0 = 0.f, a1 = 0.f, a2 = 0.f, a3 = 0.f;
    for (int i = s; i < e; ++i) {
        int2 cv = g_edges[i];
        float v = __int_as_float(cv.y);
        const float* xr = x + (size_t)cv.x * EMB;
        a0 = fmaf(v, __ldg(xr + lane),      a0);
        a1 = fmaf(v, __ldg(xr + lane + 32), a1);
        a2 = fmaf(v, __ldg(xr + lane + 64), a2);
        if (lane < 4) a3 = fmaf(v, __ldg(xr + lane + 96), a3);
    }
    a0 *= g; a1 *= g; a2 *= g; a3 *= g;

    float* ar = acc + (size_t)row * EMB;
    ar[lane]      += a0;
    ar[lane + 32] += a1;
    ar[lane + 64] += a2;
    if (lane < 4) ar[lane + 96] += a3;

    if (y) {
        float* yr = y + (size_t)row * EMB;
        yr[lane]      = a0;
        yr[lane + 32] = a1;
        yr[lane + 64] = a2;
        if (lane < 4) yr[lane + 96] = a3;
    }
}

// ---------------- history SpMM (tiny, warp per edge, atomic scatter) -------
__global__ void k_zero_hist() {
    int i = blockIdx.x * blockDim.x + threadIdx.x;
    if (i < BATCH * HIST_MAX * EMB) g_hist[i] = 0.f;
}

__global__ void k_hist_spmm(const int* __restrict__ hr,
                            const int* __restrict__ hc,
                            const float* __restrict__ hv,
                            const float* __restrict__ item) {
    int e    = (blockIdx.x * blockDim.x + threadIdx.x) >> 5;
    int lane = threadIdx.x & 31;
    if (e >= NNZ_H) return;
    int   r = hr[e];
    int   c = hc[e];
    float v = hv[e];
    const float* xr = item + (size_t)c * EMB;
    float* yr = g_hist + (size_t)r * EMB;
    atomicAdd(&yr[lane],      v * __ldg(xr + lane));
    atomicAdd(&yr[lane + 32], v * __ldg(xr + lane + 32));
    atomicAdd(&yr[lane + 64], v * __ldg(xr + lane + 64));
    if (lane < 4) atomicAdd(&yr[lane + 96], v * __ldg(xr + lane + 96));
}

// ---------------- attention + softmax + weighted sum (1 block / batch) -----
__global__ void k_attention(const int* __restrict__ hist_len,
                            const int* __restrict__ user,
                            const float* __restrict__ uemb,
                            const float* __restrict__ W1,
                            float* __restrict__ out_user) {
    int b = blockIdx.x;                 // 0..99
    int t = threadIdx.x;                // 128 threads
    int lane = t & 31, w = t >> 5;

    __shared__ float s_w1a[EMB], s_w1b[EMB];
    __shared__ float s_alpha[HIST_MAX];
    __shared__ float s_dotu;

    if (t < EMB) { s_w1a[t] = W1[t]; s_w1b[t] = W1[EMB + t]; }
    __syncthreads();

    int u   = user[b];
    int len = hist_len[b];

    // dot(user_emb, W1[:E])
    if (w == 0) {
        float s = 0.f;
        const float* ur = uemb + (size_t)u * EMB;
        for (int e = lane; e < EMB; e += 32) s += ur[e] * s_w1a[e];
        for (int o = 16; o; o >>= 1) s += __shfl_down_sync(0xFFFFFFFFu, s, o);
        if (lane == 0) s_dotu = s;
    }
    __syncthreads();
    float dotu = s_dotu;

    // per-history-slot logits
    for (int h = w; h < HIST_MAX; h += 4) {
        const float* hrow = g_hist + ((size_t)b * HIST_MAX + h) * EMB;
        float s = 0.f;
        for (int e = lane; e < EMB; e += 32) s += hrow[e] * s_w1b[e];
        for (int o = 16; o; o >>= 1) s += __shfl_down_sync(0xFFFFFFFFu, s, o);
        if (lane == 0) s_alpha[h] = dotu + s + (h >= len ? -99999.0f : 0.0f);
    }
    __syncthreads();

    // softmax over 50 (warp 0)
    if (w == 0) {
        float m = -1e30f;
        for (int h = lane; h < HIST_MAX; h += 32) m = fmaxf(m, s_alpha[h]);
        for (int o = 16; o; o >>= 1) m = fmaxf(m, __shfl_xor_sync(0xFFFFFFFFu, m, o));
        float sum = 0.f;
        for (int h = lane; h < HIST_MAX; h += 32) {
            float ex = expf(s_alpha[h] - m);
            s_alpha[h] = ex;
            sum += ex;
        }
        for (int o = 16; o; o >>= 1) sum += __shfl_xor_sync(0xFFFFFFFFu, sum, o);
        float inv = 1.0f / sum;
        for (int h = lane; h < HIST_MAX; h += 32) s_alpha[h] *= inv;
    }
    __syncthreads();

    float invd = (len == 0) ? 1.0f : 1.0f / (float)len;
    if (t < EMB) {
        float a = 0.f;
        const float* base = g_hist + (size_t)b * HIST_MAX * EMB + t;
        #pragma unroll 5
        for (int h = 0; h < HIST_MAX; ++h) a += s_alpha[h] * base[h * EMB];
        out_user[b * EMB + t] = a * invd;
    }
}

// ---------------- launch ----------------
extern "C" void kernel_launch(void* const* d_in, const int* in_sizes, int n_in,
                              void* d_out, int out_size) {
    const int*   adj_row  = (const int*)  d_in[0];
    const int*   adj_col  = (const int*)  d_in[1];
    const float* adj_val  = (const float*)d_in[2];
    const int*   hist_row = (const int*)  d_in[3];
    const int*   hist_col = (const int*)  d_in[4];
    const float* hist_val = (const float*)d_in[5];
    const int*   hist_len = (const int*)  d_in[6];
    const int*   user     = (const int*)  d_in[7];
    const float* embedding      = (const float*)d_in[8];
    const float* user_embedding = (const float*)d_in[9];
    const float* gamma_k = (const float*)d_in[10];
    const float* W_1     = (const float*)d_in[11];

    float* out      = (float*)d_out;                       // [N_ITEMS, EMB]
    float* out_user = out + (size_t)N_ITEMS * EMB;         // [BATCH, EMB]

    // CSR build
    k_zero_cnt<<<(N_ITEMS + 255) / 256, 256>>>();
    k_count<<<(NNZ_A + 255) / 256, 256>>>(adj_row);
    k_scan1<<<NCHUNKS, 1024>>>();
    k_scan2<<<1, 32>>>();
    k_scan3<<<NCHUNKS, 1024>>>();
    k_scatter<<<(NNZ_A + 255) / 256, 256>>>(adj_row, adj_col, adj_val);

    // acc = embedding * gamma[0]
    {
        const size_t n4 = (size_t)N_ITEMS * EMB / 4;
        k_init_acc<<<(unsigned)((n4 + 255) / 256), 256>>>(
            (const float4*)embedding, gamma_k, (float4*)out);
    }

    // 3 propagation layers (warp per row; 8 rows/block)
    const int spmm_blocks = (N_ITEMS + 7) / 8;
    k_spmm<<<spmm_blocks, 256>>>(embedding, g_buf0, out, gamma_k + 1);
    k_spmm<<<spmm_blocks, 256>>>(g_buf0,    g_buf1, out, gamma_k + 2);
    k_spmm<<<spmm_blocks, 256>>>(g_buf1,    nullptr, out, gamma_k + 3);

    // history aggregation + attention
    k_zero_hist<<<(BATCH * HIST_MAX * EMB + 255) / 256, 256>>>();
    k_hist_spmm<<<(NNZ_H * 32 + 255) / 256, 256>>>(hist_row, hist_col, hist_val, out);
    k_attention<<<BATCH, 128>>>(hist_len, user, user_embedding, W_1, out_user);
}

// round 10
// speedup vs baseline: 1.0014x; 1.0014x over previous
#include <cuda_runtime.h>

#define N_ITEMS  200000
#define EMB      100
#define BATCH    100
#define HIST_MAX 50
#define NNZ_A    6400000
#define NNZ_H    25000
#define NCHUNKS  ((N_ITEMS + 1023) / 1024)

// ---------------- device scratch (no allocations allowed) ----------------
__device__ int   g_cnt[N_ITEMS];
__device__ int   g_rowstart[N_ITEMS + 1];
__device__ int   g_cursor[N_ITEMS];
__device__ int   g_chunksums[NCHUNKS];
__device__ int2  g_edges[NNZ_A];                    // (col, val-as-int) sorted by row
__device__ float g_buf0[(size_t)N_ITEMS * EMB];
__device__ float g_buf1[(size_t)N_ITEMS * EMB];
__device__ float g_hist[BATCH * HIST_MAX * EMB];

// ---------------- CSR build: histogram + scan + scatter ----------------
__global__ void k_zero_cnt() {
    int i = blockIdx.x * blockDim.x + threadIdx.x;
    if (i < N_ITEMS) g_cnt[i] = 0;
}

__global__ void k_count(const int* __restrict__ rows) {
    int i = blockIdx.x * blockDim.x + threadIdx.x;
    if (i < NNZ_A) atomicAdd(&g_cnt[rows[i]], 1);
}

// per-chunk (1024) sums
__global__ void k_scan1() {
    __shared__ int wsum[32];
    int tid = threadIdx.x, lane = tid & 31, w = tid >> 5;
    int i = blockIdx.x * 1024 + tid;
    int v = (i < N_ITEMS) ? g_cnt[i] : 0;
    for (int o = 16; o; o >>= 1) v += __shfl_down_sync(0xFFFFFFFFu, v, o);
    if (lane == 0) wsum[w] = v;
    __syncthreads();
    if (w == 0) {
        int s = wsum[lane];
        for (int o = 16; o; o >>= 1) s += __shfl_down_sync(0xFFFFFFFFu, s, o);
        if (lane == 0) g_chunksums[blockIdx.x] = s;
    }
}

// serial exclusive scan of 196 chunk sums (tiny)
__global__ void k_scan2() {
    if (threadIdx.x == 0) {
        int run = 0;
        for (int i = 0; i < NCHUNKS; i++) {
            int v = g_chunksums[i];
            g_chunksums[i] = run;
            run += v;
        }
        g_rowstart[N_ITEMS] = run;
    }
}

// per-chunk exclusive scan + chunk offset -> row_start / cursor
__global__ void k_scan3() {
    __shared__ int wsum[32];
    int tid = threadIdx.x, lane = tid & 31, w = tid >> 5;
    int i = blockIdx.x * 1024 + tid;
    int v = (i < N_ITEMS) ? g_cnt[i] : 0;
    int x = v;
    for (int o = 1; o < 32; o <<= 1) {
        int y = __shfl_up_sync(0xFFFFFFFFu, x, o);
        if (lane >= o) x += y;
    }
    if (lane == 31) wsum[w] = x;
    __syncthreads();
    if (w == 0) {
        int s = wsum[lane];
        for (int o = 1; o < 32; o <<= 1) {
            int y = __shfl_up_sync(0xFFFFFFFFu, s, o);
            if (lane >= o) s += y;
        }
        wsum[lane] = s;   // inclusive warp sums
    }
    __syncthreads();
    int woff = (w == 0) ? 0 : wsum[w - 1];
    int excl = x - v + woff + g_chunksums[blockIdx.x];
    if (i < N_ITEMS) {
        g_rowstart[i] = excl;
        g_cursor[i]   = excl;
    }
}

__global__ void k_scatter(const int* __restrict__ rows,
                          const int* __restrict__ cols,
                          const float* __restrict__ vals) {
    int i = blockIdx.x * blockDim.x + threadIdx.x;
    if (i >= NNZ_A) return;
    int r = rows[i];
    int p = atomicAdd(&g_cursor[r], 1);
    g_edges[p] = make_int2(cols[i], __float_as_int(vals[i]));
}

// ---------------- acc init: out = embedding * gamma[0] ----------------
__global__ void k_init_acc(const float4* __restrict__ emb4,
                           const float* __restrict__ gamma,
                           float4* __restrict__ out4) {
    size_t i = (size_t)blockIdx.x * blockDim.x + threadIdx.x;
    const size_t n4 = (size_t)N_ITEMS * EMB / 4;   // 5,000,000
    float g = gamma[0];
    if (i < n4) {
        float4 e = emb4[i];
        out4[i] = make_float4(e.x * g, e.y * g, e.z * g, e.w * g);
    }
}

// ---------------- CSR SpMM: warp per row, fused gamma + acc ----------------
__global__ void k_spmm(const float* __restrict__ x,
                       float* __restrict__ y,            // may be null (last layer)
                       float* __restrict__ acc,
                       const float* __restrict__ gammap) {
    int row  = blockIdx.x * (blockDim.x >> 5) + (threadIdx.x >> 5);
    int lane = threadIdx.x & 31;
    if (row >= N_ITEMS) return;
    float g = *gammap;
    int s = g_rowstart[row], e = g_rowstart[row + 1];

    float a0 = 0.f, a1 = 0.f, a2 = 0.f, a3 = 0.f;
    for (int i = s; i < e; ++i) {
        int2 cv = g_edges[i];
        float v = __int_as_float(cv.y);
        const float* xr = x + (size_t)cv.x * EMB;
        a0 = fmaf(v, __ldg(xr + lane),      a0);
        a1 = fmaf(v, __ldg(xr + lane + 32), a1);
        a2 = fmaf(v, __ldg(xr + lane + 64), a2);
        if (lane < 4) a3 = fmaf(v, __ldg(xr + lane + 96), a3);
    }
    a0 *= g; a1 *= g; a2 *= g; a3 *= g;

    float* ar = acc + (size_t)row * EMB;
    ar[lane]      += a0;
    ar[lane + 32] += a1;
    ar[lane + 64] += a2;
    if (lane < 4) ar[lane + 96] += a3;

    if (y) {
        float* yr = y + (size_t)row * EMB;
        yr[lane]      = a0;
        yr[lane + 32] = a1;
        yr[lane + 64] = a2;
        if (lane < 4) yr[lane + 96] = a3;
    }
}

// ---------------- history SpMM (tiny, warp per edge, atomic scatter) -------
__global__ void k_zero_hist() {
    int i = blockIdx.x * blockDim.x + threadIdx.x;
    if (i < BATCH * HIST_MAX * EMB) g_hist[i] = 0.f;
}

__global__ void k_hist_spmm(const int* __restrict__ hr,
                            const int* __restrict__ hc,
                            const float* __restrict__ hv,
                            const float* __restrict__ item) {
    int e    = (blockIdx.x * blockDim.x + threadIdx.x) >> 5;
    int lane = threadIdx.x & 31;
    if (e >= NNZ_H) return;
    int   r = hr[e];
    int   c = hc[e];
    float v = hv[e];
    const float* xr = item + (size_t)c * EMB;
    float* yr = g_hist + (size_t)r * EMB;
    atomicAdd(&yr[lane],      v * __ldg(xr + lane));
    atomicAdd(&yr[lane + 32], v * __ldg(xr + lane + 32));
    atomicAdd(&yr[lane + 64], v * __ldg(xr + lane + 64));
    if (lane < 4) atomicAdd(&yr[lane + 96], v * __ldg(xr + lane + 96));
}

// ---------------- attention + softmax + weighted sum (1 block / batch) -----
__global__ void k_attention(const int* __restrict__ hist_len,
                            const int* __restrict__ user,
                            const float* __restrict__ uemb,
                            const float* __restrict__ W1,
                            float* __restrict__ out_user) {
    int b = blockIdx.x;                 // 0..99
    int t = threadIdx.x;                // 128 threads
    int lane = t & 31, w = t >> 5;

    __shared__ float s_w1a[EMB], s_w1b[EMB];
    __shared__ float s_alpha[HIST_MAX];
    __shared__ float s_dotu;

    if (t < EMB) { s_w1a[t] = W1[t]; s_w1b[t] = W1[EMB + t]; }
    __syncthreads();

    int u   = user[b];
    int len = hist_len[b];

    // dot(user_emb, W1[:E])
    if (w == 0) {
        float s = 0.f;
        const float* ur = uemb + (size_t)u * EMB;
        for (int e = lane; e < EMB; e += 32) s += ur[e] * s_w1a[e];
        for (int o = 16; o; o >>= 1) s += __shfl_down_sync(0xFFFFFFFFu, s, o);
        if (lane == 0) s_dotu = s;
    }
    __syncthreads();
    float dotu = s_dotu;

    // per-history-slot logits
    for (int h = w; h < HIST_MAX; h += 4) {
        const float* hrow = g_hist + ((size_t)b * HIST_MAX + h) * EMB;
        float s = 0.f;
        for (int e = lane; e < EMB; e += 32) s += hrow[e] * s_w1b[e];
        for (int o = 16; o; o >>= 1) s += __shfl_down_sync(0xFFFFFFFFu, s, o);
        if (lane == 0) s_alpha[h] = dotu + s + (h >= len ? -99999.0f : 0.0f);
    }
    __syncthreads();

    // softmax over 50 (warp 0)
    if (w == 0) {
        float m = -1e30f;
        for (int h = lane; h < HIST_MAX; h += 32) m = fmaxf(m, s_alpha[h]);
        for (int o = 16; o; o >>= 1) m = fmaxf(m, __shfl_xor_sync(0xFFFFFFFFu, m, o));
        float sum = 0.f;
        for (int h = lane; h < HIST_MAX; h += 32) {
            float ex = expf(s_alpha[h] - m);
            s_alpha[h] = ex;
            sum += ex;
        }
        for (int o = 16; o; o >>= 1) sum += __shfl_xor_sync(0xFFFFFFFFu, sum, o);
        float inv = 1.0f / sum;
        for (int h = lane; h < HIST_MAX; h += 32) s_alpha[h] *= inv;
    }
    __syncthreads();

    float invd = (len == 0) ? 1.0f : 1.0f / (float)len;
    if (t < EMB) {
        float a = 0.f;
        const float* base = g_hist + (size_t)b * HIST_MAX * EMB + t;
        #pragma unroll 5
        for (int h = 0; h < HIST_MAX; ++h) a += s_alpha[h] * base[h * EMB];
        out_user[b * EMB + t] = a * invd;
    }
}

// ---------------- launch ----------------
extern "C" void kernel_launch(void* const* d_in, const int* in_sizes, int n_in,
                              void* d_out, int out_size) {
    const int*   adj_row  = (const int*)  d_in[0];
    const int*   adj_col  = (const int*)  d_in[1];
    const float* adj_val  = (const float*)d_in[2];
    const int*   hist_row = (const int*)  d_in[3];
    const int*   hist_col = (const int*)  d_in[4];
    const float* hist_val = (const float*)d_in[5];
    const int*   hist_len = (const int*)  d_in[6];
    const int*   user     = (const int*)  d_in[7];
    const float* embedding      = (const float*)d_in[8];
    const float* user_embedding = (const float*)d_in[9];
    const float* gamma_k = (const float*)d_in[10];
    const float* W_1     = (const float*)d_in[11];

    float* out      = (float*)d_out;                       // [N_ITEMS, EMB]
    float* out_user = out + (size_t)N_ITEMS * EMB;         // [BATCH, EMB]

    // CSR build
    k_zero_cnt<<<(N_ITEMS + 255) / 256, 256>>>();
    k_count<<<(NNZ_A + 255) / 256, 256>>>(adj_row);
    k_scan1<<<NCHUNKS, 1024>>>();
    k_scan2<<<1, 32>>>();
    k_scan3<<<NCHUNKS, 1024>>>();
    k_scatter<<<(NNZ_A + 255) / 256, 256>>>(adj_row, adj_col, adj_val);

    // acc = embedding * gamma[0]
    {
        const size_t n4 = (size_t)N_ITEMS * EMB / 4;
        k_init_acc<<<(unsigned)((n4 + 255) / 256), 256>>>(
            (const float4*)embedding, gamma_k, (float4*)out);
    }

    // 3 propagation layers (warp per row; 8 rows/block)
    const int spmm_blocks = (N_ITEMS + 7) / 8;
    k_spmm<<<spmm_blocks, 256>>>(embedding, g_buf0, out, gamma_k + 1);
    k_spmm<<<spmm_blocks, 256>>>(g_buf0,    g_buf1, out, gamma_k + 2);
    k_spmm<<<spmm_blocks, 256>>>(g_buf1,    nullptr, out, gamma_k + 3);

    // history aggregation + attention
    k_zero_hist<<<(BATCH * HIST_MAX * EMB + 255) / 256, 256>>>();
    k_hist_spmm<<<(NNZ_H * 32 + 255) / 256, 256>>>(hist_row, hist_col, hist_val, out);
    k_attention<<<BATCH, 128>>>(hist_len, user, user_embedding, W_1, out_user);
}

// round 11
// speedup vs baseline: 1.0551x; 1.0536x over previous
#include <cuda_runtime.h>

#define N_ITEMS  200000
#define EMB      100
#define EMB4     25
#define BATCH    100
#define HIST_MAX 50
#define NNZ_A    6400000
#define NNZ_H    25000
#define NCHUNKS  ((N_ITEMS + 1023) / 1024)

// ---------------- device scratch (no allocations allowed) ----------------
__device__ int    g_cnt[N_ITEMS];
__device__ int    g_rowstart[N_ITEMS + 1];
__device__ int    g_cursor[N_ITEMS];
__device__ int    g_chunksums[NCHUNKS];
__device__ int2   g_edges[NNZ_A];                         // (col, val) sorted by row
__device__ float4 g_buf0[(size_t)N_ITEMS * EMB4];         // float4 => 16B aligned
__device__ float4 g_buf1[(size_t)N_ITEMS * EMB4];
__device__ float  g_hist[BATCH * HIST_MAX * EMB];

// ---------------- CSR build: histogram + scan + scatter ----------------
__global__ void k_count(const int* __restrict__ rows) {
    int i = blockIdx.x * blockDim.x + threadIdx.x;
    if (i < NNZ_A) atomicAdd(&g_cnt[rows[i]], 1);
}

__global__ void k_scan1() {
    __shared__ int wsum[32];
    int tid = threadIdx.x, lane = tid & 31, w = tid >> 5;
    int i = blockIdx.x * 1024 + tid;
    int v = (i < N_ITEMS) ? g_cnt[i] : 0;
    for (int o = 16; o; o >>= 1) v += __shfl_down_sync(0xFFFFFFFFu, v, o);
    if (lane == 0) wsum[w] = v;
    __syncthreads();
    if (w == 0) {
        int s = wsum[lane];
        for (int o = 16; o; o >>= 1) s += __shfl_down_sync(0xFFFFFFFFu, s, o);
        if (lane == 0) g_chunksums[blockIdx.x] = s;
    }
}

__global__ void k_scan2() {
    if (threadIdx.x == 0) {
        int run = 0;
        for (int i = 0; i < NCHUNKS; i++) {
            int v = g_chunksums[i];
            g_chunksums[i] = run;
            run += v;
        }
        g_rowstart[N_ITEMS] = run;
    }
}

__global__ void k_scan3() {
    __shared__ int wsum[32];
    int tid = threadIdx.x, lane = tid & 31, w = tid >> 5;
    int i = blockIdx.x * 1024 + tid;
    int v = (i < N_ITEMS) ? g_cnt[i] : 0;
    int x = v;
    for (int o = 1; o < 32; o <<= 1) {
        int y = __shfl_up_sync(0xFFFFFFFFu, x, o);
        if (lane >= o) x += y;
    }
    if (lane == 31) wsum[w] = x;
    __syncthreads();
    if (w == 0) {
        int s = wsum[lane];
        for (int o = 1; o < 32; o <<= 1) {
            int y = __shfl_up_sync(0xFFFFFFFFu, s, o);
            if (lane >= o) s += y;
        }
        wsum[lane] = s;
    }
    __syncthreads();
    int woff = (w == 0) ? 0 : wsum[w - 1];
    int excl = x - v + woff + g_chunksums[blockIdx.x];
    if (i < N_ITEMS) {
        g_rowstart[i] = excl;
        g_cursor[i]   = excl;
    }
}

__global__ void k_scatter(const int* __restrict__ rows,
                          const int* __restrict__ cols,
                          const float* __restrict__ vals) {
    int i = blockIdx.x * blockDim.x + threadIdx.x;
    if (i >= NNZ_A) return;
    int r = rows[i];
    int p = atomicAdd(&g_cursor[r], 1);
    g_edges[p] = make_int2(cols[i], __float_as_int(vals[i]));
}

// ---------------- CSR SpMM: warp/row, float4 lanes, 4x unrolled ----------
__device__ __forceinline__ float4 fma4(float w, float4 v, float4 a) {
    a.x = fmaf(w, v.x, a.x);
    a.y = fmaf(w, v.y, a.y);
    a.z = fmaf(w, v.z, a.z);
    a.w = fmaf(w, v.w, a.w);
    return a;
}

// layer 1: acc = embedding*gamma0 + result*gamma1  (init fused, no RMW pass)
// layers 2/3: acc += result*gamma_k.  y (next input) = result*gamma_k.
__global__ void __launch_bounds__(256) k_spmm(
        const float4* __restrict__ x4,     // gather source  [N_ITEMS, 25]
        float4* __restrict__ y4,           // next-layer buf or null
        float4* __restrict__ acc4,         // output accumulator
        const float4* __restrict__ init4,  // embedding (layer 1) or null
        const float* __restrict__ gammas,  // gamma_k base
        int layer) {
    int row  = blockIdx.x * (blockDim.x >> 5) + (threadIdx.x >> 5);
    int lane = threadIdx.x & 31;
    if (row >= N_ITEMS) return;

    float g = __ldg(gammas + layer);
    int s = g_rowstart[row], e = g_rowstart[row + 1];
    int li = lane < EMB4 ? lane : (EMB4 - 1);   // lanes 25..31 alias lane 24 (no divergence)

    float4 A = {0.f,0.f,0.f,0.f}, B = A, C = A, D = A;
    int i = s;
    for (; i + 4 <= e; i += 4) {
        int2 e0 = __ldcs(&g_edges[i]);
        int2 e1 = __ldcs(&g_edges[i + 1]);
        int2 e2 = __ldcs(&g_edges[i + 2]);
        int2 e3 = __ldcs(&g_edges[i + 3]);
        float4 v0 = __ldg(x4 + (size_t)e0.x * EMB4 + li);
        float4 v1 = __ldg(x4 + (size_t)e1.x * EMB4 + li);
        float4 v2 = __ldg(x4 + (size_t)e2.x * EMB4 + li);
        float4 v3 = __ldg(x4 + (size_t)e3.x * EMB4 + li);
        A = fma4(__int_as_float(e0.y), v0, A);
        B = fma4(__int_as_float(e1.y), v1, B);
        C = fma4(__int_as_float(e2.y), v2, C);
        D = fma4(__int_as_float(e3.y), v3, D);
    }
    for (; i < e; ++i) {
        int2 ev = __ldcs(&g_edges[i]);
        float4 v = __ldg(x4 + (size_t)ev.x * EMB4 + li);
        A = fma4(__int_as_float(ev.y), v, A);
    }
    A.x = (A.x + B.x + C.x + D.x) * g;
    A.y = (A.y + B.y + C.y + D.y) * g;
    A.z = (A.z + B.z + C.z + D.z) * g;
    A.w = (A.w + B.w + C.w + D.w) * g;

    if (lane < EMB4) {
        size_t off = (size_t)row * EMB4 + lane;
        float4 base;
        if (init4) {
            float g0 = __ldg(gammas);
            float4 t = __ldg(init4 + off);
            base = make_float4(t.x * g0, t.y * g0, t.z * g0, t.w * g0);
        } else {
            base = __ldcs(acc4 + off);      // streaming RMW, don't pollute L2
        }
        base.x += A.x; base.y += A.y; base.z += A.z; base.w += A.w;
        __stcs(acc4 + off, base);
        if (y4) y4[off] = A;                // next-layer gather target: keep cacheable
    }
}

// ---------------- history SpMM (tiny, warp per edge, atomic scatter) -------
__global__ void k_hist_spmm(const int* __restrict__ hr,
                            const int* __restrict__ hc,
                            const float* __restrict__ hv,
                            const float* __restrict__ item) {
    int e    = (blockIdx.x * blockDim.x + threadIdx.x) >> 5;
    int lane = threadIdx.x & 31;
    if (e >= NNZ_H) return;
    int   r = hr[e];
    int   c = hc[e];
    float v = hv[e];
    const float* xr = item + (size_t)c * EMB;
    float* yr = g_hist + (size_t)r * EMB;
    atomicAdd(&yr[lane],      v * __ldg(xr + lane));
    atomicAdd(&yr[lane + 32], v * __ldg(xr + lane + 32));
    atomicAdd(&yr[lane + 64], v * __ldg(xr + lane + 64));
    if (lane < 4) atomicAdd(&yr[lane + 96], v * __ldg(xr + lane + 96));
}

// ---------------- attention + softmax + weighted sum (1 block / batch) -----
__global__ void k_attention(const int* __restrict__ hist_len,
                            const int* __restrict__ user,
                            const float* __restrict__ uemb,
                            const float* __restrict__ W1,
                            float* __restrict__ out_user) {
    int b = blockIdx.x;
    int t = threadIdx.x;
    int lane = t & 31, w = t >> 5;

    __shared__ float s_w1a[EMB], s_w1b[EMB];
    __shared__ float s_alpha[HIST_MAX];
    __shared__ float s_dotu;

    if (t < EMB) { s_w1a[t] = W1[t]; s_w1b[t] = W1[EMB + t]; }
    __syncthreads();

    int u   = user[b];
    int len = hist_len[b];

    if (w == 0) {
        float s = 0.f;
        const float* ur = uemb + (size_t)u * EMB;
        for (int e = lane; e < EMB; e += 32) s += ur[e] * s_w1a[e];
        for (int o = 16; o; o >>= 1) s += __shfl_down_sync(0xFFFFFFFFu, s, o);
        if (lane == 0) s_dotu = s;
    }
    __syncthreads();
    float dotu = s_dotu;

    for (int h = w; h < HIST_MAX; h += 4) {
        const float* hrow = g_hist + ((size_t)b * HIST_MAX + h) * EMB;
        float s = 0.f;
        for (int e = lane; e < EMB; e += 32) s += hrow[e] * s_w1b[e];
        for (int o = 16; o; o >>= 1) s += __shfl_down_sync(0xFFFFFFFFu, s, o);
        if (lane == 0) s_alpha[h] = dotu + s + (h >= len ? -99999.0f : 0.0f);
    }
    __syncthreads();

    if (w == 0) {
        float m = -1e30f;
        for (int h = lane; h < HIST_MAX; h += 32) m = fmaxf(m, s_alpha[h]);
        for (int o = 16; o; o >>= 1) m = fmaxf(m, __shfl_xor_sync(0xFFFFFFFFu, m, o));
        float sum = 0.f;
        for (int h = lane; h < HIST_MAX; h += 32) {
            float ex = expf(s_alpha[h] - m);
            s_alpha[h] = ex;
            sum += ex;
        }
        for (int o = 16; o; o >>= 1) sum += __shfl_xor_sync(0xFFFFFFFFu, sum, o);
        float inv = 1.0f / sum;
        for (int h = lane; h < HIST_MAX; h += 32) s_alpha[h] *= inv;
    }
    __syncthreads();

    float invd = (len == 0) ? 1.0f : 1.0f / (float)len;
    if (t < EMB) {
        float a = 0.f;
        const float* base = g_hist + (size_t)b * HIST_MAX * EMB + t;
        #pragma unroll 5
        for (int h = 0; h < HIST_MAX; ++h) a += s_alpha[h] * base[h * EMB];
        out_user[b * EMB + t] = a * invd;
    }
}

// ---------------- launch ----------------
extern "C" void kernel_launch(void* const* d_in, const int* in_sizes, int n_in,
                              void* d_out, int out_size) {
    const int*   adj_row  = (const int*)  d_in[0];
    const int*   adj_col  = (const int*)  d_in[1];
    const float* adj_val  = (const float*)d_in[2];
    const int*   hist_row = (const int*)  d_in[3];
    const int*   hist_col = (const int*)  d_in[4];
    const float* hist_val = (const float*)d_in[5];
    const int*   hist_len = (const int*)  d_in[6];
    const int*   user     = (const int*)  d_in[7];
    const float* embedding      = (const float*)d_in[8];
    const float* user_embedding = (const float*)d_in[9];
    const float* gamma_k = (const float*)d_in[10];
    const float* W_1     = (const float*)d_in[11];

    float*  out      = (float*)d_out;                     // [N_ITEMS, EMB]
    float*  out_user = out + (size_t)N_ITEMS * EMB;       // [BATCH, EMB]
    float4* out4     = (float4*)out;
    const float4* emb4 = (const float4*)embedding;

    void *p_cnt = nullptr, *p_hist = nullptr;
    cudaGetSymbolAddress(&p_cnt,  g_cnt);
    cudaGetSymbolAddress(&p_hist, g_hist);

    // CSR build (memsets instead of zero-kernels; capturable, no allocs)
    cudaMemsetAsync(p_cnt,  0, N_ITEMS * sizeof(int));
    cudaMemsetAsync(p_hist, 0, BATCH * HIST_MAX * EMB * sizeof(float));
    k_count<<<(NNZ_A + 255) / 256, 256>>>(adj_row);
    k_scan1<<<NCHUNKS, 1024>>>();
    k_scan2<<<1, 32>>>();
    k_scan3<<<NCHUNKS, 1024>>>();
    k_scatter<<<(NNZ_A + 255) / 256, 256>>>(adj_row, adj_col, adj_val);

    // 3 propagation layers (warp per row; 8 rows/block; layer 1 fuses init)
    const int spmm_blocks = (N_ITEMS + 7) / 8;
    k_spmm<<<spmm_blocks, 256>>>(emb4,   g_buf0,  out4, emb4,    gamma_k, 1);
    k_spmm<<<spmm_blocks, 256>>>(g_buf0, g_buf1,  out4, nullptr, gamma_k, 2);
    k_spmm<<<spmm_blocks, 256>>>(g_buf1, nullptr, out4, nullptr, gamma_k, 3);

    // history aggregation + attention
    k_hist_spmm<<<(NNZ_H * 32 + 255) / 256, 256>>>(hist_row, hist_col, hist_val, out);
    k_attention<<<BATCH, 128>>>(hist_len, user, user_embedding, W_1, out_user);
}